// round 1
// baseline (speedup 1.0000x reference)
#include <cuda_runtime.h>
#include <cuda_bf16.h>
#include <stdint.h>

#define Q_N   4096
#define D_N   32768
#define DIM   128
#define TQ    128
#define TD    128
#define LDSK  136          // padded k-stride in bf16 elems: row r shifts banks by 4 -> conflict-free quads
#define NSLICE 32
#define SUBS  ((D_N / TD) / NSLICE)   // 8 D-subtiles per CTA

// ---- device scratch (no allocations allowed) ----
__device__ __nv_bfloat16 g_qh[Q_N * DIM];
__device__ __nv_bfloat16 g_ql[Q_N * DIM];
__device__ __nv_bfloat16 g_dh[D_N * DIM];
__device__ __nv_bfloat16 g_dl[D_N * DIM];
__device__ unsigned long long g_key[Q_N];

// =====================================================================
// Pass 0: fp32 -> (bf16 hi, bf16 lo) split; also reset per-query max keys
// =====================================================================
__global__ void convert_kernel(const float* __restrict__ qe, const float* __restrict__ de) {
    int i = blockIdx.x * blockDim.x + threadIdx.x;
    if (i < D_N * DIM) {
        float x = de[i];
        __nv_bfloat16 h = __float2bfloat16(x);                 // round-to-nearest
        g_dh[i] = h;
        g_dl[i] = __float2bfloat16(x - __bfloat162float(h));
    }
    if (i < Q_N * DIM) {
        float x = qe[i];
        __nv_bfloat16 h = __float2bfloat16(x);
        g_qh[i] = h;
        g_ql[i] = __float2bfloat16(x - __bfloat162float(h));
    }
    if (i < Q_N) g_key[i] = 0ull;                              // key 0 == -inf
}

// =====================================================================
// helpers
// =====================================================================
__device__ __forceinline__ void cpa16(void* s, const void* g) {
    unsigned sa = (unsigned)__cvta_generic_to_shared(s);
    asm volatile("cp.async.cg.shared.global [%0], [%1], 16;\n" :: "r"(sa), "l"(g));
}

// load a [128 x 128] bf16 tile (row-major, gmem stride DIM) into smem with stride LDSK
__device__ __forceinline__ void load_tile(__nv_bfloat16* dst, const __nv_bfloat16* gsrc, int tid) {
#pragma unroll
    for (int t = 0; t < 8; t++) {
        int chunk = tid + t * 256;          // 2048 16B-chunks total
        int row = chunk >> 4;
        int c   = chunk & 15;
        cpa16(dst + row * LDSK + c * 8, gsrc + row * DIM + c * 8);
    }
}

__device__ __forceinline__ void mma16816(float* c,
                                         uint32_t a0, uint32_t a1, uint32_t a2, uint32_t a3,
                                         uint32_t b0, uint32_t b1) {
    asm volatile(
        "mma.sync.aligned.m16n8k16.row.col.f32.bf16.bf16.f32 "
        "{%0,%1,%2,%3}, {%4,%5,%6,%7}, {%8,%9}, {%0,%1,%2,%3};\n"
        : "+f"(c[0]), "+f"(c[1]), "+f"(c[2]), "+f"(c[3])
        : "r"(a0), "r"(a1), "r"(a2), "r"(a3), "r"(b0), "r"(b1));
}

// order-preserving (float,argmin-on-tie) 64-bit key for atomicMax
__device__ __forceinline__ unsigned long long pack_key(float v, unsigned col) {
    unsigned u = __float_as_uint(v);
    u = (u & 0x80000000u) ? ~u : (u | 0x80000000u);
    return ((unsigned long long)u << 32) | (unsigned long long)(0xFFFFFFFFu - col);
}

// =====================================================================
// Pass 1: bf16x3 GEMM + running row-max/argmax + atomic merge
// =====================================================================
__global__ __launch_bounds__(256, 1) void maxsim_kernel() {
    extern __shared__ __nv_bfloat16 sm[];
    __nv_bfloat16* Ah    = sm;
    __nv_bfloat16* Al    = Ah + TQ * LDSK;
    __nv_bfloat16* Bbase = Al + TQ * LDSK;    // 2 buffers x (hi tile, lo tile)

    const int tid  = threadIdx.x;
    const int wid  = tid >> 5;
    const int lane = tid & 31;
    const int g    = lane >> 2;     // row group within mma tile
    const int qr   = lane & 3;      // quad rank (col/k subposition)
    const int qtile = blockIdx.x;
    const int d0    = blockIdx.y * (SUBS * TD);
    const int arow  = wid * 16 + g;

    // prologue: A (hi+lo) once, B subtile 0 (hi+lo)
    load_tile(Ah, g_qh + qtile * TQ * DIM, tid);
    load_tile(Al, g_ql + qtile * TQ * DIM, tid);
    load_tile(Bbase,             g_dh + d0 * DIM, tid);
    load_tile(Bbase + TD * LDSK, g_dl + d0 * DIM, tid);
    asm volatile("cp.async.commit_group;\n");

    float    rmax0 = -3.402823466e38f, rmax1 = -3.402823466e38f;
    unsigned rcol0 = 0, rcol1 = 0;

    for (int s = 0; s < SUBS; s++) {
        asm volatile("cp.async.wait_group 0;\n");
        __syncthreads();                          // tile (s) ready; everyone done with tile (s-1)
        if (s + 1 < SUBS) {                       // prefetch next B subtile into other buffer
            __nv_bfloat16* nb = Bbase + ((s + 1) & 1) * (2 * TD * LDSK);
            load_tile(nb,             g_dh + (d0 + (s + 1) * TD) * DIM, tid);
            load_tile(nb + TD * LDSK, g_dl + (d0 + (s + 1) * TD) * DIM, tid);
            asm volatile("cp.async.commit_group;\n");
        }
        const __nv_bfloat16* bh = Bbase + (s & 1) * (2 * TD * LDSK);
        const __nv_bfloat16* bl = bh + TD * LDSK;

        float acc[16][4];
#pragma unroll
        for (int nt = 0; nt < 16; nt++) {
#pragma unroll
            for (int i = 0; i < 4; i++) acc[nt][i] = 0.f;
        }

#pragma unroll 2
        for (int ks = 0; ks < 8; ks++) {
            const int k0 = ks * 16 + qr * 2;
            uint32_t ah0 = *(const uint32_t*)&Ah[ arow      * LDSK + k0    ];
            uint32_t ah1 = *(const uint32_t*)&Ah[(arow + 8) * LDSK + k0    ];
            uint32_t ah2 = *(const uint32_t*)&Ah[ arow      * LDSK + k0 + 8];
            uint32_t ah3 = *(const uint32_t*)&Ah[(arow + 8) * LDSK + k0 + 8];
            uint32_t al0 = *(const uint32_t*)&Al[ arow      * LDSK + k0    ];
            uint32_t al1 = *(const uint32_t*)&Al[(arow + 8) * LDSK + k0    ];
            uint32_t al2 = *(const uint32_t*)&Al[ arow      * LDSK + k0 + 8];
            uint32_t al3 = *(const uint32_t*)&Al[(arow + 8) * LDSK + k0 + 8];
#pragma unroll
            for (int nt = 0; nt < 16; nt++) {
                const int n = nt * 8 + g;
                uint32_t bh0 = *(const uint32_t*)&bh[n * LDSK + k0    ];
                uint32_t bh1 = *(const uint32_t*)&bh[n * LDSK + k0 + 8];
                uint32_t bl0 = *(const uint32_t*)&bl[n * LDSK + k0    ];
                uint32_t bl1 = *(const uint32_t*)&bl[n * LDSK + k0 + 8];
                mma16816(acc[nt], ah0, ah1, ah2, ah3, bh0, bh1);  // hi*hi
                mma16816(acc[nt], ah0, ah1, ah2, ah3, bl0, bl1);  // hi*lo
                mma16816(acc[nt], al0, al1, al2, al3, bh0, bh1);  // lo*hi
            }
        }

        // running max/argmax (columns strictly ascending -> strict '>' keeps first index)
        const int dbase = d0 + s * TD + qr * 2;
#pragma unroll
        for (int nt = 0; nt < 16; nt++) {
            unsigned c0 = (unsigned)(dbase + nt * 8);
            if (acc[nt][0] > rmax0) { rmax0 = acc[nt][0]; rcol0 = c0;     }
            if (acc[nt][1] > rmax0) { rmax0 = acc[nt][1]; rcol0 = c0 + 1; }
            if (acc[nt][2] > rmax1) { rmax1 = acc[nt][2]; rcol1 = c0;     }
            if (acc[nt][3] > rmax1) { rmax1 = acc[nt][3]; rcol1 = c0 + 1; }
        }
    }

    // reduce across the 4 lanes sharing each row; ties -> smaller column
#pragma unroll
    for (int off = 1; off < 4; off <<= 1) {
        float    om0 = __shfl_xor_sync(0xffffffffu, rmax0, off);
        unsigned oc0 = __shfl_xor_sync(0xffffffffu, rcol0, off);
        if (om0 > rmax0 || (om0 == rmax0 && oc0 < rcol0)) { rmax0 = om0; rcol0 = oc0; }
        float    om1 = __shfl_xor_sync(0xffffffffu, rmax1, off);
        unsigned oc1 = __shfl_xor_sync(0xffffffffu, rcol1, off);
        if (om1 > rmax1 || (om1 == rmax1 && oc1 < rcol1)) { rmax1 = om1; rcol1 = oc1; }
    }
    if (qr == 0) {
        atomicMax(&g_key[qtile * TQ + arow    ], pack_key(rmax0, rcol0));
        atomicMax(&g_key[qtile * TQ + arow + 8], pack_key(rmax1, rcol1));
    }
}

// =====================================================================
// Pass 2: unpack (max,argmax), gather weights, normalized weighted sum
// =====================================================================
__global__ void finalize_kernel(const int* __restrict__ qids, const int* __restrict__ dids,
                                const float* __restrict__ qwt, const float* __restrict__ dwt,
                                float* __restrict__ out) {
    __shared__ float sA[256], sB[256], sC[256];
    int tid = threadIdx.x;
    float a = 0.f, b = 0.f, c = 0.f;
    for (int q = tid; q < Q_N; q += 256) {
        unsigned long long k = g_key[q];
        unsigned u    = (unsigned)(k >> 32);
        unsigned bits = (u & 0x80000000u) ? (u & 0x7FFFFFFFu) : ~u;
        float    ms   = __uint_as_float(bits);
        unsigned col  = 0xFFFFFFFFu - (unsigned)(k & 0xFFFFFFFFu);
        float comb = qwt[qids[q]] * dwt[dids[col]];
        a += comb;
        b += comb * ms;
        c += ms;
    }
    sA[tid] = a; sB[tid] = b; sC[tid] = c;
    __syncthreads();
    for (int off = 128; off > 0; off >>= 1) {
        if (tid < off) { sA[tid] += sA[tid + off]; sB[tid] += sB[tid + off]; sC[tid] += sC[tid + off]; }
        __syncthreads();
    }
    if (tid == 0) {
        out[0] = (sA[0] > 0.f) ? (sB[0] / sA[0]) : (sC[0] / (float)Q_N);
    }
}

// =====================================================================
// launch
// =====================================================================
extern "C" void kernel_launch(void* const* d_in, const int* in_sizes, int n_in,
                              void* d_out, int out_size) {
    const float* qe  = (const float*)d_in[0];
    const float* de  = (const float*)d_in[1];
    const int*   qid = (const int*)d_in[2];
    const int*   did = (const int*)d_in[3];
    const float* qwt = (const float*)d_in[4];
    const float* dwt = (const float*)d_in[5];
    float* out = (float*)d_out;

    size_t smem = (size_t)(2 * TQ + 4 * TD) * LDSK * sizeof(__nv_bfloat16);   // 208,896 B
    cudaFuncSetAttribute(maxsim_kernel, cudaFuncAttributeMaxDynamicSharedMemorySize, (int)smem);

    convert_kernel<<<(D_N * DIM + 255) / 256, 256>>>(qe, de);
    maxsim_kernel<<<dim3(Q_N / TQ, NSLICE), 256, smem>>>();
    finalize_kernel<<<1, 256>>>(qid, did, qwt, dwt, out);
}

// round 3
// speedup vs baseline: 1.0726x; 1.0726x over previous
#include <cuda_runtime.h>
#include <cuda_bf16.h>
#include <stdint.h>

#define Q_N   4096
#define D_N   32768
#define DIM   128
#define TQ    128
#define TN    128
#define LDSK  136                    // padded row stride in bf16 elems (272 B)
#define ROWB  272                    // bytes per smem row
#define NSLICE 32
#define SUBS  ((D_N / TN) / NSLICE)  // 8 D-subtiles per CTA
#define TILE_E (TQ * LDSK)           // elems per 128-row tile

// ---- device scratch ----
__device__ __nv_bfloat16 g_qh[Q_N * DIM];
__device__ __nv_bfloat16 g_ql[Q_N * DIM];
__device__ __nv_bfloat16 g_dh[D_N * DIM];
__device__ __nv_bfloat16 g_dl[D_N * DIM];
__device__ unsigned long long g_key[Q_N];

// ---- helpers ----
__device__ __forceinline__ uint32_t smem_u32(const void* p) {
    uint32_t a;
    asm("{ .reg .u64 t; cvta.to.shared.u64 t, %1; cvt.u32.u64 %0, t; }" : "=r"(a) : "l"(p));
    return a;
}
__device__ __forceinline__ void cpa16(void* s, const void* g) {
    unsigned sa = smem_u32(s);
    asm volatile("cp.async.cg.shared.global [%0], [%1], 16;" :: "r"(sa), "l"(g));
}
#define CP_COMMIT() asm volatile("cp.async.commit_group;" ::: "memory")
#define CP_WAIT0()  asm volatile("cp.async.wait_group 0;" ::: "memory")

// load a [128 x 128] bf16 tile (gmem row stride DIM) into smem rows of stride LDSK
__device__ __forceinline__ void load_tile(__nv_bfloat16* dst, const __nv_bfloat16* gsrc, int tid) {
#pragma unroll
    for (int t = 0; t < 8; t++) {
        int chunk = tid + t * 256;      // 2048 16B chunks
        int row = chunk >> 4;
        int c   = chunk & 15;
        cpa16(dst + row * LDSK + c * 8, gsrc + row * DIM + c * 8);
    }
}

__device__ __forceinline__ void ldm_x4(uint32_t* r, uint32_t addr) {
    asm volatile("ldmatrix.sync.aligned.m8n8.x4.shared.b16 {%0,%1,%2,%3}, [%4];"
        : "=r"(r[0]), "=r"(r[1]), "=r"(r[2]), "=r"(r[3]) : "r"(addr));
}

__device__ __forceinline__ void mma16816(float* c, const uint32_t* a, uint32_t b0, uint32_t b1) {
    asm volatile(
        "mma.sync.aligned.m16n8k16.row.col.f32.bf16.bf16.f32 "
        "{%0,%1,%2,%3}, {%4,%5,%6,%7}, {%8,%9}, {%0,%1,%2,%3};\n"
        : "+f"(c[0]), "+f"(c[1]), "+f"(c[2]), "+f"(c[3])
        : "r"(a[0]), "r"(a[1]), "r"(a[2]), "r"(a[3]), "r"(b0), "r"(b1));
}

__device__ __forceinline__ unsigned long long pack_key(float v, unsigned col) {
    unsigned u = __float_as_uint(v);
    u = (u & 0x80000000u) ? ~u : (u | 0x80000000u);
    return ((unsigned long long)u << 32) | (unsigned long long)(0xFFFFFFFFu - col);
}

// =====================================================================
// Pass 0: fp32 -> (bf16 hi, lo) split, float4-vectorized; reset keys
// =====================================================================
__global__ void convert_kernel(const float4* __restrict__ qe, const float4* __restrict__ de) {
    int i = blockIdx.x * blockDim.x + threadIdx.x;
    if (i < D_N * DIM / 4) {
        float4 v = de[i];
        float xs[4] = {v.x, v.y, v.z, v.w};
        __nv_bfloat16 hh[4], ll[4];
#pragma unroll
        for (int k = 0; k < 4; k++) {
            hh[k] = __float2bfloat16(xs[k]);
            ll[k] = __float2bfloat16(xs[k] - __bfloat162float(hh[k]));
        }
        ((__nv_bfloat162*)g_dh)[2 * i]     = __halves2bfloat162(hh[0], hh[1]);
        ((__nv_bfloat162*)g_dh)[2 * i + 1] = __halves2bfloat162(hh[2], hh[3]);
        ((__nv_bfloat162*)g_dl)[2 * i]     = __halves2bfloat162(ll[0], ll[1]);
        ((__nv_bfloat162*)g_dl)[2 * i + 1] = __halves2bfloat162(ll[2], ll[3]);
    }
    if (i < Q_N * DIM / 4) {
        float4 v = qe[i];
        float xs[4] = {v.x, v.y, v.z, v.w};
        __nv_bfloat16 hh[4], ll[4];
#pragma unroll
        for (int k = 0; k < 4; k++) {
            hh[k] = __float2bfloat16(xs[k]);
            ll[k] = __float2bfloat16(xs[k] - __bfloat162float(hh[k]));
        }
        ((__nv_bfloat162*)g_qh)[2 * i]     = __halves2bfloat162(hh[0], hh[1]);
        ((__nv_bfloat162*)g_qh)[2 * i + 1] = __halves2bfloat162(hh[2], hh[3]);
        ((__nv_bfloat162*)g_ql)[2 * i]     = __halves2bfloat162(ll[0], ll[1]);
        ((__nv_bfloat162*)g_ql)[2 * i + 1] = __halves2bfloat162(ll[2], ll[3]);
    }
    if (i < Q_N) g_key[i] = 0ull;
}

// =====================================================================
// Pass 1: bf16x3 mma.sync GEMM, warp tile 32Mx64N, ldmatrix fragments,
//         fused running row max/argmax
// =====================================================================
__global__ __launch_bounds__(256, 1) void maxsim_kernel() {
    extern __shared__ __nv_bfloat16 sm[];
    __nv_bfloat16* Ah    = sm;                 // [128 x LDSK]
    __nv_bfloat16* Al    = Ah + TILE_E;
    __nv_bfloat16* Bbase = Al + TILE_E;        // 2 buffers x (hi tile, lo tile)

    const int tid  = threadIdx.x;
    const int wid  = tid >> 5;
    const int lane = tid & 31;
    const int g    = lane >> 2;
    const int qr   = lane & 3;
    const int wid_m = wid >> 1;                // 0..3
    const int wid_n = wid & 1;                 // 0..1
    const int qtile = blockIdx.x;
    const int d0    = blockIdx.y * (SUBS * TN);

    // prologue: A (hi+lo), B subtile 0 (hi+lo)
    load_tile(Ah, g_qh + (size_t)qtile * TQ * DIM, tid);
    load_tile(Al, g_ql + (size_t)qtile * TQ * DIM, tid);
    load_tile(Bbase,          g_dh + (size_t)d0 * DIM, tid);
    load_tile(Bbase + TILE_E, g_dl + (size_t)d0 * DIM, tid);
    CP_COMMIT();

    // per-lane ldmatrix base addresses (bytes)
    const int rowA  = wid_m * 32 + (lane & 15);
    const int colAb = ((lane >> 4) & 1) * 16;          // k-half byte offset
    const uint32_t aH_base = smem_u32(Ah) + rowA * ROWB + colAb;
    const uint32_t aL_base = smem_u32(Al) + rowA * ROWB + colAb;
    const int rowB  = wid_n * 64 + (lane & 7) + ((lane >> 4) << 3);
    const int colBb = ((lane >> 3) & 1) * 16;
    const uint32_t b_lane_off = (uint32_t)(rowB * ROWB + colBb);
    const uint32_t b_smem0 = smem_u32(Bbase);

    float    rmax[4] = {-3.402823466e38f, -3.402823466e38f, -3.402823466e38f, -3.402823466e38f};
    unsigned rcol[4] = {0, 0, 0, 0};

    for (int s = 0; s < SUBS; s++) {
        CP_WAIT0();
        __syncthreads();                        // B[s] ready; all warps done with buffer being overwritten
        if (s + 1 < SUBS) {
            __nv_bfloat16* nb = Bbase + ((s + 1) & 1) * (2 * TILE_E);
            load_tile(nb,          g_dh + (size_t)(d0 + (s + 1) * TN) * DIM, tid);
            load_tile(nb + TILE_E, g_dl + (size_t)(d0 + (s + 1) * TN) * DIM, tid);
            CP_COMMIT();
        }
        const uint32_t bH_base = b_smem0 + (uint32_t)(s & 1) * (2 * TILE_E * 2) + b_lane_off;
        const uint32_t bL_base = bH_base + TILE_E * 2;

        float acc[2][8][4];
#pragma unroll
        for (int mt = 0; mt < 2; mt++)
#pragma unroll
            for (int nt = 0; nt < 8; nt++)
#pragma unroll
                for (int i = 0; i < 4; i++) acc[mt][nt][i] = 0.f;

#pragma unroll
        for (int ks = 0; ks < 8; ks++) {
            const uint32_t ko = (uint32_t)(ks * 32);
            uint32_t aH[2][4], aL[2][4];
            ldm_x4(aH[0], aH_base + ko);
            ldm_x4(aH[1], aH_base + 16 * ROWB + ko);
            ldm_x4(aL[0], aL_base + ko);
            ldm_x4(aL[1], aL_base + 16 * ROWB + ko);
            uint32_t bH[4][4], bL[4][4];
#pragma unroll
            for (int p = 0; p < 4; p++) {
                ldm_x4(bH[p], bH_base + (uint32_t)(p * 16 * ROWB) + ko);
                ldm_x4(bL[p], bL_base + (uint32_t)(p * 16 * ROWB) + ko);
            }
#pragma unroll
            for (int mt = 0; mt < 2; mt++) {
#pragma unroll
                for (int p = 0; p < 4; p++) {
                    // n-tile 2p (matrices 0,1) and 2p+1 (matrices 2,3)
                    mma16816(acc[mt][2 * p],     aH[mt], bH[p][0], bH[p][1]);   // hi*hi
                    mma16816(acc[mt][2 * p],     aH[mt], bL[p][0], bL[p][1]);   // hi*lo
                    mma16816(acc[mt][2 * p],     aL[mt], bH[p][0], bH[p][1]);   // lo*hi
                    mma16816(acc[mt][2 * p + 1], aH[mt], bH[p][2], bH[p][3]);
                    mma16816(acc[mt][2 * p + 1], aH[mt], bL[p][2], bL[p][3]);
                    mma16816(acc[mt][2 * p + 1], aL[mt], bH[p][2], bH[p][3]);
                }
            }
        }

        // running max/argmax; columns strictly ascending -> '>' keeps first index
        const int cb = d0 + s * TN + wid_n * 64 + qr * 2;
#pragma unroll
        for (int mt = 0; mt < 2; mt++) {
#pragma unroll
            for (int nt = 0; nt < 8; nt++) {
                unsigned c0 = (unsigned)(cb + nt * 8);
                float v0 = acc[mt][nt][0], v1 = acc[mt][nt][1];
                float v2 = acc[mt][nt][2], v3 = acc[mt][nt][3];
                if (v0 > rmax[mt * 2])     { rmax[mt * 2]     = v0; rcol[mt * 2]     = c0;     }
                if (v1 > rmax[mt * 2])     { rmax[mt * 2]     = v1; rcol[mt * 2]     = c0 + 1; }
                if (v2 > rmax[mt * 2 + 1]) { rmax[mt * 2 + 1] = v2; rcol[mt * 2 + 1] = c0;     }
                if (v3 > rmax[mt * 2 + 1]) { rmax[mt * 2 + 1] = v3; rcol[mt * 2 + 1] = c0 + 1; }
            }
        }
    }

    // reduce across the 4 lanes (qr) sharing each row; ties -> smaller column
#pragma unroll
    for (int off = 1; off < 4; off <<= 1) {
#pragma unroll
        for (int r = 0; r < 4; r++) {
            float    om = __shfl_xor_sync(0xffffffffu, rmax[r], off);
            unsigned oc = __shfl_xor_sync(0xffffffffu, rcol[r], off);
            if (om > rmax[r] || (om == rmax[r] && oc < rcol[r])) { rmax[r] = om; rcol[r] = oc; }
        }
    }
    if (qr == 0) {
        int row0 = qtile * TQ + wid_m * 32 + g;
        atomicMax(&g_key[row0     ], pack_key(rmax[0], rcol[0]));
        atomicMax(&g_key[row0 +  8], pack_key(rmax[1], rcol[1]));
        atomicMax(&g_key[row0 + 16], pack_key(rmax[2], rcol[2]));
        atomicMax(&g_key[row0 + 24], pack_key(rmax[3], rcol[3]));
    }
}

// =====================================================================
// Pass 2: unpack (max,argmax), gather weights, normalized weighted sum
// =====================================================================
__global__ void finalize_kernel(const int* __restrict__ qids, const int* __restrict__ dids,
                                const float* __restrict__ qwt, const float* __restrict__ dwt,
                                float* __restrict__ out) {
    __shared__ float sA[256], sB[256], sC[256];
    int tid = threadIdx.x;
    float a = 0.f, b = 0.f, c = 0.f;
    for (int q = tid; q < Q_N; q += 256) {
        unsigned long long k = g_key[q];
        unsigned u    = (unsigned)(k >> 32);
        unsigned bits = (u & 0x80000000u) ? (u & 0x7FFFFFFFu) : ~u;
        float    ms   = __uint_as_float(bits);
        unsigned col  = 0xFFFFFFFFu - (unsigned)(k & 0xFFFFFFFFu);
        float comb = qwt[qids[q]] * dwt[dids[col]];
        a += comb; b += comb * ms; c += ms;
    }
    sA[tid] = a; sB[tid] = b; sC[tid] = c;
    __syncthreads();
    for (int off = 128; off > 0; off >>= 1) {
        if (tid < off) { sA[tid] += sA[tid + off]; sB[tid] += sB[tid + off]; sC[tid] += sC[tid + off]; }
        __syncthreads();
    }
    if (tid == 0) out[0] = (sA[0] > 0.f) ? (sB[0] / sA[0]) : (sC[0] / (float)Q_N);
}

// =====================================================================
// launch
// =====================================================================
extern "C" void kernel_launch(void* const* d_in, const int* in_sizes, int n_in,
                              void* d_out, int out_size) {
    const float* qe  = (const float*)d_in[0];
    const float* de  = (const float*)d_in[1];
    const int*   qid = (const int*)d_in[2];
    const int*   did = (const int*)d_in[3];
    const float* qwt = (const float*)d_in[4];
    const float* dwt = (const float*)d_in[5];
    float* out = (float*)d_out;

    size_t smem = (size_t)(6 * TILE_E) * sizeof(__nv_bfloat16);   // 208,896 B
    cudaFuncSetAttribute(maxsim_kernel, cudaFuncAttributeMaxDynamicSharedMemorySize, (int)smem);

    convert_kernel<<<(D_N * DIM / 4 + 255) / 256, 256>>>((const float4*)qe, (const float4*)de);
    maxsim_kernel<<<dim3(Q_N / TQ, NSLICE), 256, smem>>>();
    finalize_kernel<<<1, 256>>>(qid, did, qwt, dwt, out);
}

// round 4
// speedup vs baseline: 1.6913x; 1.5768x over previous
#include <cuda_runtime.h>
#include <cuda_bf16.h>
#include <stdint.h>

#define Q_N   4096
#define D_N   32768
#define DIM   128
#define TQ    128
#define TN    128
#define LDSK  136                    // padded smem row stride (272 B)
#define ROWB  272
#define NSLICE 32
#define SUBS  ((D_N / TN) / NSLICE)  // 8 D-subtiles per CTA
#define TILE_E (TQ * LDSK)
#define NBLK  (D_N / 8)              // 4096 8-col blocks per row
#define MARGIN 3.0f

// ---- device scratch ----
__device__ __nv_bfloat16 g_qh[Q_N * DIM];
__device__ __nv_bfloat16 g_dh[D_N * DIM];
__device__ float    g_lmax[(size_t)Q_N * NBLK];        // 64 MB
__device__ uint32_t g_cands[(size_t)Q_N * 512];        // 8 MB cap
__device__ int      g_ccount;
__device__ unsigned long long g_key[Q_N];

// ---- helpers ----
__device__ __forceinline__ uint32_t smem_u32(const void* p) {
    uint32_t a;
    asm("{ .reg .u64 t; cvta.to.shared.u64 t, %1; cvt.u32.u64 %0, t; }" : "=r"(a) : "l"(p));
    return a;
}
__device__ __forceinline__ void cpa16(void* s, const void* g) {
    unsigned sa = smem_u32(s);
    asm volatile("cp.async.cg.shared.global [%0], [%1], 16;" :: "r"(sa), "l"(g));
}
#define CP_COMMIT() asm volatile("cp.async.commit_group;" ::: "memory")
#define CP_WAIT0()  asm volatile("cp.async.wait_group 0;" ::: "memory")

__device__ __forceinline__ void load_tile(__nv_bfloat16* dst, const __nv_bfloat16* gsrc, int tid) {
#pragma unroll
    for (int t = 0; t < 8; t++) {
        int chunk = tid + t * 256;
        int row = chunk >> 4;
        int c   = chunk & 15;
        cpa16(dst + row * LDSK + c * 8, gsrc + row * DIM + c * 8);
    }
}
__device__ __forceinline__ void ldm_x4(uint32_t* r, uint32_t addr) {
    asm volatile("ldmatrix.sync.aligned.m8n8.x4.shared.b16 {%0,%1,%2,%3}, [%4];"
        : "=r"(r[0]), "=r"(r[1]), "=r"(r[2]), "=r"(r[3]) : "r"(addr));
}
__device__ __forceinline__ void mma16816(float* c, const uint32_t* a, uint32_t b0, uint32_t b1) {
    asm volatile(
        "mma.sync.aligned.m16n8k16.row.col.f32.bf16.bf16.f32 "
        "{%0,%1,%2,%3}, {%4,%5,%6,%7}, {%8,%9}, {%0,%1,%2,%3};\n"
        : "+f"(c[0]), "+f"(c[1]), "+f"(c[2]), "+f"(c[3])
        : "r"(a[0]), "r"(a[1]), "r"(a[2]), "r"(a[3]), "r"(b0), "r"(b1));
}
__device__ __forceinline__ unsigned long long pack_key(float v, unsigned col) {
    unsigned u = __float_as_uint(v);
    u = (u & 0x80000000u) ? ~u : (u | 0x80000000u);
    return ((unsigned long long)u << 32) | (unsigned long long)(0xFFFFFFFFu - col);
}

// =====================================================================
// Pass 0: fp32 -> bf16 hi (round-to-nearest); reset keys + counter
// =====================================================================
__global__ void convert_kernel(const float4* __restrict__ qe, const float4* __restrict__ de) {
    int i = blockIdx.x * blockDim.x + threadIdx.x;
    if (i < D_N * DIM / 4) {
        float4 v = de[i];
        ((__nv_bfloat162*)g_dh)[2 * i]     = __halves2bfloat162(__float2bfloat16(v.x), __float2bfloat16(v.y));
        ((__nv_bfloat162*)g_dh)[2 * i + 1] = __halves2bfloat162(__float2bfloat16(v.z), __float2bfloat16(v.w));
    }
    if (i < Q_N * DIM / 4) {
        float4 v = qe[i];
        ((__nv_bfloat162*)g_qh)[2 * i]     = __halves2bfloat162(__float2bfloat16(v.x), __float2bfloat16(v.y));
        ((__nv_bfloat162*)g_qh)[2 * i + 1] = __halves2bfloat162(__float2bfloat16(v.z), __float2bfloat16(v.w));
    }
    if (i < Q_N) g_key[i] = 0ull;
    if (i == 0)  g_ccount = 0;
}

// =====================================================================
// Pass 1: bf16 hi*hi GEMM (mma.sync), per-(row, 8-col block) max table
// =====================================================================
__global__ __launch_bounds__(256, 2) void approx_kernel() {
    extern __shared__ __nv_bfloat16 sm[];
    __nv_bfloat16* Ah    = sm;                 // [128 x LDSK]
    __nv_bfloat16* Bbase = Ah + TILE_E;        // 2 x [128 x LDSK]

    const int tid  = threadIdx.x;
    const int wid  = tid >> 5;
    const int lane = tid & 31;
    const int g    = lane >> 2;
    const int qr   = lane & 3;
    const int wid_m = wid >> 1;
    const int wid_n = wid & 1;
    const int qtile = blockIdx.x;
    const int d0    = blockIdx.y * (SUBS * TN);

    load_tile(Ah, g_qh + (size_t)qtile * TQ * DIM, tid);
    load_tile(Bbase, g_dh + (size_t)d0 * DIM, tid);
    CP_COMMIT();

    const int rowA  = wid_m * 32 + (lane & 15);
    const int colAb = ((lane >> 4) & 1) * 16;
    const uint32_t aH_base = smem_u32(Ah) + rowA * ROWB + colAb;
    const int rowB  = wid_n * 64 + (lane & 7) + ((lane >> 4) << 3);
    const int colBb = ((lane >> 3) & 1) * 16;
    const uint32_t b_lane_off = (uint32_t)(rowB * ROWB + colBb);
    const uint32_t b_smem0 = smem_u32(Bbase);

    const int row0 = qtile * TQ + wid_m * 32 + g;

    for (int s = 0; s < SUBS; s++) {
        CP_WAIT0();
        __syncthreads();
        if (s + 1 < SUBS) {
            load_tile(Bbase + ((s + 1) & 1) * TILE_E, g_dh + (size_t)(d0 + (s + 1) * TN) * DIM, tid);
            CP_COMMIT();
        }
        const uint32_t bH_base = b_smem0 + (uint32_t)(s & 1) * (TILE_E * 2) + b_lane_off;

        float acc[2][8][4];
#pragma unroll
        for (int mt = 0; mt < 2; mt++)
#pragma unroll
            for (int nt = 0; nt < 8; nt++)
#pragma unroll
                for (int i = 0; i < 4; i++) acc[mt][nt][i] = 0.f;

#pragma unroll
        for (int ks = 0; ks < 8; ks++) {
            const uint32_t ko = (uint32_t)(ks * 32);
            uint32_t aH[2][4];
            ldm_x4(aH[0], aH_base + ko);
            ldm_x4(aH[1], aH_base + 16 * ROWB + ko);
            uint32_t bH[4][4];
#pragma unroll
            for (int p = 0; p < 4; p++)
                ldm_x4(bH[p], bH_base + (uint32_t)(p * 16 * ROWB) + ko);
#pragma unroll
            for (int mt = 0; mt < 2; mt++)
#pragma unroll
                for (int p = 0; p < 4; p++) {
                    mma16816(acc[mt][2 * p],     aH[mt], bH[p][0], bH[p][1]);
                    mma16816(acc[mt][2 * p + 1], aH[mt], bH[p][2], bH[p][3]);
                }
        }

        // per (row-slot, 8-col block) max; reduce over quad ranks (cols)
        float bm[4][8];
#pragma unroll
        for (int nt = 0; nt < 8; nt++) {
            bm[0][nt] = fmaxf(acc[0][nt][0], acc[0][nt][1]);
            bm[1][nt] = fmaxf(acc[0][nt][2], acc[0][nt][3]);
            bm[2][nt] = fmaxf(acc[1][nt][0], acc[1][nt][1]);
            bm[3][nt] = fmaxf(acc[1][nt][2], acc[1][nt][3]);
        }
#pragma unroll
        for (int off = 1; off < 4; off <<= 1)
#pragma unroll
            for (int sl = 0; sl < 4; sl++)
#pragma unroll
                for (int nt = 0; nt < 8; nt++)
                    bm[sl][nt] = fmaxf(bm[sl][nt], __shfl_xor_sync(0xffffffffu, bm[sl][nt], off));

        if (qr == 0) {
            const int gblk = (blockIdx.y * SUBS + s) * 16 + wid_n * 8;
#pragma unroll
            for (int sl = 0; sl < 4; sl++) {
                float* dst = g_lmax + (size_t)(row0 + sl * 8) * NBLK + gblk;
                ((float4*)dst)[0] = make_float4(bm[sl][0], bm[sl][1], bm[sl][2], bm[sl][3]);
                ((float4*)dst)[1] = make_float4(bm[sl][4], bm[sl][5], bm[sl][6], bm[sl][7]);
            }
        }
    }
}

// =====================================================================
// Pass 2: per-row threshold scan -> candidate block list
// =====================================================================
__global__ void scan_kernel() {
    const int row = blockIdx.x;
    const int t   = threadIdx.x;     // 256
    __shared__ float red[256];
    __shared__ int lcnt, base;
    __shared__ uint32_t lbuf[512];

    const float4* lm4 = (const float4*)(g_lmax + (size_t)row * NBLK);
    float m = -3.402823466e38f;
#pragma unroll
    for (int j = t; j < NBLK / 4; j += 256) {
        float4 v = lm4[j];
        m = fmaxf(m, fmaxf(fmaxf(v.x, v.y), fmaxf(v.z, v.w)));
    }
    red[t] = m;
    __syncthreads();
    for (int off = 128; off > 0; off >>= 1) {
        if (t < off) red[t] = fmaxf(red[t], red[t + off]);
        __syncthreads();
    }
    const float thr = red[0] - MARGIN;
    if (t == 0) lcnt = 0;
    __syncthreads();

    const float* lm = g_lmax + (size_t)row * NBLK;
    for (int j = t; j < NBLK; j += 256) {
        if (lm[j] >= thr) {
            int p = atomicAdd(&lcnt, 1);
            if (p < 512) lbuf[p] = ((uint32_t)row << 12) | (uint32_t)j;
        }
    }
    __syncthreads();
    int cnt = lcnt < 512 ? lcnt : 512;
    if (t == 0) base = atomicAdd(&g_ccount, cnt);
    __syncthreads();
    for (int j = t; j < cnt; j += 256) g_cands[base + j] = lbuf[j];
}

// =====================================================================
// Pass 3: exact fp32 recompute of candidate blocks -> packed key atomicMax
// =====================================================================
__global__ void exact_kernel(const float* __restrict__ qe, const float* __restrict__ de) {
    const int gw    = (blockIdx.x * blockDim.x + threadIdx.x) >> 5;
    const int lane  = threadIdx.x & 31;
    const int sub   = lane >> 3;     // 4 entries per warp
    const int cl    = lane & 7;
    const int nwarp = (gridDim.x * blockDim.x) >> 5;
    const int n     = g_ccount;

    for (int e0 = gw * 4; e0 < n; e0 += nwarp * 4) {
        const int e = e0 + sub;
        const bool valid = (e < n);
        uint32_t ent = valid ? g_cands[e] : 0u;
        const int row = (int)(ent >> 12);
        const int col = (int)(ent & 4095u) * 8 + cl;

        float s = -3.402823466e38f;
        if (valid) {
            const float4* q4 = (const float4*)(qe + (size_t)row * DIM);
            const float4* d4 = (const float4*)(de + (size_t)col * DIM);
            float acc = 0.f;
#pragma unroll
            for (int k = 0; k < DIM / 4; k++) {
                float4 a = q4[k], b = d4[k];
                acc = fmaf(a.x, b.x, acc);
                acc = fmaf(a.y, b.y, acc);
                acc = fmaf(a.z, b.z, acc);
                acc = fmaf(a.w, b.w, acc);
            }
            s = acc;
        }
        unsigned c = (unsigned)col;
#pragma unroll
        for (int off = 1; off < 8; off <<= 1) {
            float    os = __shfl_xor_sync(0xffffffffu, s, off);
            unsigned oc = __shfl_xor_sync(0xffffffffu, c, off);
            if (os > s || (os == s && oc < c)) { s = os; c = oc; }
        }
        if (valid && cl == 0) atomicMax(&g_key[row], pack_key(s, c));
    }
}

// =====================================================================
// Pass 4: gather weights, normalized weighted sum
// =====================================================================
__global__ void finalize_kernel(const int* __restrict__ qids, const int* __restrict__ dids,
                                const float* __restrict__ qwt, const float* __restrict__ dwt,
                                float* __restrict__ out) {
    __shared__ float sA[256], sB[256], sC[256];
    int tid = threadIdx.x;
    float a = 0.f, b = 0.f, c = 0.f;
    for (int q = tid; q < Q_N; q += 256) {
        unsigned long long k = g_key[q];
        unsigned u    = (unsigned)(k >> 32);
        unsigned bits = (u & 0x80000000u) ? (u & 0x7FFFFFFFu) : ~u;
        float    ms   = __uint_as_float(bits);
        unsigned col  = 0xFFFFFFFFu - (unsigned)(k & 0xFFFFFFFFu);
        float comb = qwt[qids[q]] * dwt[dids[col]];
        a += comb; b += comb * ms; c += ms;
    }
    sA[tid] = a; sB[tid] = b; sC[tid] = c;
    __syncthreads();
    for (int off = 128; off > 0; off >>= 1) {
        if (tid < off) { sA[tid] += sA[tid + off]; sB[tid] += sB[tid + off]; sC[tid] += sC[tid + off]; }
        __syncthreads();
    }
    if (tid == 0) out[0] = (sA[0] > 0.f) ? (sB[0] / sA[0]) : (sC[0] / (float)Q_N);
}

// =====================================================================
// launch
// =====================================================================
extern "C" void kernel_launch(void* const* d_in, const int* in_sizes, int n_in,
                              void* d_out, int out_size) {
    const float* qe  = (const float*)d_in[0];
    const float* de  = (const float*)d_in[1];
    const int*   qid = (const int*)d_in[2];
    const int*   did = (const int*)d_in[3];
    const float* qwt = (const float*)d_in[4];
    const float* dwt = (const float*)d_in[5];
    float* out = (float*)d_out;

    size_t smem = (size_t)(3 * TILE_E) * sizeof(__nv_bfloat16);   // 104,448 B -> 2 CTAs/SM
    cudaFuncSetAttribute(approx_kernel, cudaFuncAttributeMaxDynamicSharedMemorySize, (int)smem);

    convert_kernel<<<(D_N * DIM / 4 + 255) / 256, 256>>>((const float4*)qe, (const float4*)de);
    approx_kernel<<<dim3(Q_N / TQ, NSLICE), 256, smem>>>();
    scan_kernel<<<Q_N, 256>>>();
    exact_kernel<<<512, 256>>>(qe, de);
    finalize_kernel<<<1, 256>>>(qid, did, qwt, dwt, out);
}

// round 5
// speedup vs baseline: 2.0427x; 1.2077x over previous
#include <cuda_runtime.h>
#include <cuda_bf16.h>
#include <stdint.h>

#define Q_N   4096
#define D_N   32768
#define DIM   128
#define TQ    128
#define TN    128
#define LDSK  136                    // padded smem row stride (272 B)
#define ROWB  272
#define NSLICE 32
#define SUBS  ((D_N / TN) / NSLICE)  // 8 D-subtiles per CTA
#define TILE_E (TQ * LDSK)
#define NBLK16 (D_N / 16)            // 2048 16-col blocks per row
#define MARGIN 1.25f
#define CAND_CAP 256

// ---- device scratch ----
__device__ __nv_bfloat16 g_qh[Q_N * DIM];
__device__ __nv_bfloat16 g_dh[D_N * DIM];
__device__ unsigned short g_lmax16[(size_t)Q_N * NBLK16];   // 16 MB, bf16 bits
__device__ uint32_t g_cands[(size_t)Q_N * CAND_CAP];
__device__ int      g_ccount;
__device__ unsigned long long g_key[Q_N];

// ---- helpers ----
__device__ __forceinline__ uint32_t smem_u32(const void* p) {
    uint32_t a;
    asm("{ .reg .u64 t; cvta.to.shared.u64 t, %1; cvt.u32.u64 %0, t; }" : "=r"(a) : "l"(p));
    return a;
}
__device__ __forceinline__ void cpa16(void* s, const void* g) {
    unsigned sa = smem_u32(s);
    asm volatile("cp.async.cg.shared.global [%0], [%1], 16;" :: "r"(sa), "l"(g));
}
#define CP_COMMIT() asm volatile("cp.async.commit_group;" ::: "memory")
#define CP_WAIT0()  asm volatile("cp.async.wait_group 0;" ::: "memory")

__device__ __forceinline__ void load_tile(__nv_bfloat16* dst, const __nv_bfloat16* gsrc, int tid) {
#pragma unroll
    for (int t = 0; t < 8; t++) {
        int chunk = tid + t * 256;
        int row = chunk >> 4;
        int c   = chunk & 15;
        cpa16(dst + row * LDSK + c * 8, gsrc + row * DIM + c * 8);
    }
}
__device__ __forceinline__ void ldm_x4(uint32_t* r, uint32_t addr) {
    asm volatile("ldmatrix.sync.aligned.m8n8.x4.shared.b16 {%0,%1,%2,%3}, [%4];"
        : "=r"(r[0]), "=r"(r[1]), "=r"(r[2]), "=r"(r[3]) : "r"(addr));
}
__device__ __forceinline__ void mma16816(float* c, const uint32_t* a, uint32_t b0, uint32_t b1) {
    asm volatile(
        "mma.sync.aligned.m16n8k16.row.col.f32.bf16.bf16.f32 "
        "{%0,%1,%2,%3}, {%4,%5,%6,%7}, {%8,%9}, {%0,%1,%2,%3};\n"
        : "+f"(c[0]), "+f"(c[1]), "+f"(c[2]), "+f"(c[3])
        : "r"(a[0]), "r"(a[1]), "r"(a[2]), "r"(a[3]), "r"(b0), "r"(b1));
}
__device__ __forceinline__ unsigned long long pack_key(float v, unsigned col) {
    unsigned u = __float_as_uint(v);
    u = (u & 0x80000000u) ? ~u : (u | 0x80000000u);
    return ((unsigned long long)u << 32) | (unsigned long long)(0xFFFFFFFFu - col);
}
__device__ __forceinline__ unsigned short bf16_bits(float x) {
    __nv_bfloat16 h = __float2bfloat16(x);
    return *reinterpret_cast<unsigned short*>(&h);
}
__device__ __forceinline__ float bits_bf16(unsigned short u) {
    __nv_bfloat16 h = *reinterpret_cast<__nv_bfloat16*>(&u);
    return __bfloat162float(h);
}

// =====================================================================
// Pass 0: fp32 -> bf16 hi; reset keys + counter (2 float4/thread ILP)
// =====================================================================
__global__ void convert_kernel(const float4* __restrict__ qe, const float4* __restrict__ de) {
    const int i = blockIdx.x * blockDim.x + threadIdx.x;   // 0 .. D_N*DIM/8-1
#pragma unroll
    for (int r = 0; r < 2; r++) {
        int j = i + r * (D_N * DIM / 8);
        float4 v = de[j];
        ((__nv_bfloat162*)g_dh)[2 * j]     = __halves2bfloat162(__float2bfloat16(v.x), __float2bfloat16(v.y));
        ((__nv_bfloat162*)g_dh)[2 * j + 1] = __halves2bfloat162(__float2bfloat16(v.z), __float2bfloat16(v.w));
    }
    if (i < Q_N * DIM / 4) {
        float4 v = qe[i];
        ((__nv_bfloat162*)g_qh)[2 * i]     = __halves2bfloat162(__float2bfloat16(v.x), __float2bfloat16(v.y));
        ((__nv_bfloat162*)g_qh)[2 * i + 1] = __halves2bfloat162(__float2bfloat16(v.z), __float2bfloat16(v.w));
    }
    if (i < Q_N) g_key[i] = 0ull;
    if (i == 0)  g_ccount = 0;
}

// =====================================================================
// Pass 1: bf16 hi*hi GEMM (mma.sync), per-(row, 16-col block) bf16 max
// =====================================================================
__global__ __launch_bounds__(256, 2) void approx_kernel() {
    extern __shared__ __nv_bfloat16 sm[];
    __nv_bfloat16* Ah    = sm;                 // [128 x LDSK]
    __nv_bfloat16* Bbase = Ah + TILE_E;        // 2 x [128 x LDSK]

    const int tid  = threadIdx.x;
    const int wid  = tid >> 5;
    const int lane = tid & 31;
    const int g    = lane >> 2;
    const int qr   = lane & 3;
    const int wid_m = wid >> 1;
    const int wid_n = wid & 1;
    const int qtile = blockIdx.x;
    const int d0    = blockIdx.y * (SUBS * TN);

    load_tile(Ah, g_qh + (size_t)qtile * TQ * DIM, tid);
    load_tile(Bbase, g_dh + (size_t)d0 * DIM, tid);
    CP_COMMIT();

    const int rowA  = wid_m * 32 + (lane & 15);
    const int colAb = ((lane >> 4) & 1) * 16;
    const uint32_t aH_base = smem_u32(Ah) + rowA * ROWB + colAb;
    const int rowB  = wid_n * 64 + (lane & 7) + ((lane >> 4) << 3);
    const int colBb = ((lane >> 3) & 1) * 16;
    const uint32_t b_lane_off = (uint32_t)(rowB * ROWB + colBb);
    const uint32_t b_smem0 = smem_u32(Bbase);

    const int row0 = qtile * TQ + wid_m * 32 + g;

    for (int s = 0; s < SUBS; s++) {
        CP_WAIT0();
        __syncthreads();
        if (s + 1 < SUBS) {
            load_tile(Bbase + ((s + 1) & 1) * TILE_E, g_dh + (size_t)(d0 + (s + 1) * TN) * DIM, tid);
            CP_COMMIT();
        }
        const uint32_t bH_base = b_smem0 + (uint32_t)(s & 1) * (TILE_E * 2) + b_lane_off;

        float acc[2][8][4];
#pragma unroll
        for (int mt = 0; mt < 2; mt++)
#pragma unroll
            for (int nt = 0; nt < 8; nt++)
#pragma unroll
                for (int i = 0; i < 4; i++) acc[mt][nt][i] = 0.f;

#pragma unroll
        for (int ks = 0; ks < 8; ks++) {
            const uint32_t ko = (uint32_t)(ks * 32);
            uint32_t aH[2][4];
            ldm_x4(aH[0], aH_base + ko);
            ldm_x4(aH[1], aH_base + 16 * ROWB + ko);
            uint32_t bH[4][4];
#pragma unroll
            for (int p = 0; p < 4; p++)
                ldm_x4(bH[p], bH_base + (uint32_t)(p * 16 * ROWB) + ko);
#pragma unroll
            for (int mt = 0; mt < 2; mt++)
#pragma unroll
                for (int p = 0; p < 4; p++) {
                    mma16816(acc[mt][2 * p],     aH[mt], bH[p][0], bH[p][1]);
                    mma16816(acc[mt][2 * p + 1], aH[mt], bH[p][2], bH[p][3]);
                }
        }

        // per (row-slot, 8-col group) max; reduce over quad ranks (cols)
        float bm[4][8];
#pragma unroll
        for (int nt = 0; nt < 8; nt++) {
            bm[0][nt] = fmaxf(acc[0][nt][0], acc[0][nt][1]);
            bm[1][nt] = fmaxf(acc[0][nt][2], acc[0][nt][3]);
            bm[2][nt] = fmaxf(acc[1][nt][0], acc[1][nt][1]);
            bm[3][nt] = fmaxf(acc[1][nt][2], acc[1][nt][3]);
        }
#pragma unroll
        for (int off = 1; off < 4; off <<= 1)
#pragma unroll
            for (int sl = 0; sl < 4; sl++)
#pragma unroll
                for (int nt = 0; nt < 8; nt++)
                    bm[sl][nt] = fmaxf(bm[sl][nt], __shfl_xor_sync(0xffffffffu, bm[sl][nt], off));

        if (qr == 0) {
            // 16-col blocks: 8 per subtile; this warp covers 4 (wid_n half)
            const int gblk = (blockIdx.y * SUBS + s) * 8 + wid_n * 4;
#pragma unroll
            for (int sl = 0; sl < 4; sl++) {
                ushort4 v;
                v.x = bf16_bits(fmaxf(bm[sl][0], bm[sl][1]));
                v.y = bf16_bits(fmaxf(bm[sl][2], bm[sl][3]));
                v.z = bf16_bits(fmaxf(bm[sl][4], bm[sl][5]));
                v.w = bf16_bits(fmaxf(bm[sl][6], bm[sl][7]));
                *(ushort4*)(g_lmax16 + (size_t)(row0 + sl * 8) * NBLK16 + gblk) = v;
            }
        }
    }
}

// =====================================================================
// Pass 2: single-pass per-row scan (values stay in registers)
// =====================================================================
__global__ void scan_kernel() {
    const int row = blockIdx.x;
    const int t   = threadIdx.x;     // 256 threads, 8 blocks each
    __shared__ float red[256];
    __shared__ int lcnt, base;
    __shared__ uint32_t lbuf[CAND_CAP];

    // load 8 bf16 block-maxima (uint4 = 16 B)
    uint4 raw = ((const uint4*)(g_lmax16 + (size_t)row * NBLK16))[t];
    float v[8];
    v[0] = bits_bf16((unsigned short)(raw.x & 0xFFFF));
    v[1] = bits_bf16((unsigned short)(raw.x >> 16));
    v[2] = bits_bf16((unsigned short)(raw.y & 0xFFFF));
    v[3] = bits_bf16((unsigned short)(raw.y >> 16));
    v[4] = bits_bf16((unsigned short)(raw.z & 0xFFFF));
    v[5] = bits_bf16((unsigned short)(raw.z >> 16));
    v[6] = bits_bf16((unsigned short)(raw.w & 0xFFFF));
    v[7] = bits_bf16((unsigned short)(raw.w >> 16));

    float m = v[0];
#pragma unroll
    for (int j = 1; j < 8; j++) m = fmaxf(m, v[j]);
    red[t] = m;
    __syncthreads();
    for (int off = 128; off > 0; off >>= 1) {
        if (t < off) red[t] = fmaxf(red[t], red[t + off]);
        __syncthreads();
    }
    const float thr = red[0] - MARGIN;
    if (t == 0) lcnt = 0;
    __syncthreads();

#pragma unroll
    for (int j = 0; j < 8; j++) {
        if (v[j] >= thr) {
            int p = atomicAdd(&lcnt, 1);
            if (p < CAND_CAP) lbuf[p] = ((uint32_t)row << 11) | (uint32_t)(t * 8 + j);
        }
    }
    __syncthreads();
    int cnt = lcnt < CAND_CAP ? lcnt : CAND_CAP;
    if (t == 0) base = atomicAdd(&g_ccount, cnt);
    __syncthreads();
    for (int j = t; j < cnt; j += 256) g_cands[base + j] = lbuf[j];
}

// =====================================================================
// Pass 3: exact fp32 recompute; 1 warp per candidate (16 cols x 2 halves)
// =====================================================================
__global__ void exact_kernel(const float* __restrict__ qe, const float* __restrict__ de) {
    const int warp  = (blockIdx.x * blockDim.x + threadIdx.x) >> 5;
    const int lane  = threadIdx.x & 31;
    const int nwarp = (gridDim.x * blockDim.x) >> 5;
    const int n     = g_ccount;
    const int cl    = lane & 15;     // column within 16-block
    const int half  = lane >> 4;     // dim half

    for (int e = warp; e < n; e += nwarp) {
        const uint32_t ent = g_cands[e];
        const int row = (int)(ent >> 11);
        const int col = (int)(ent & 2047u) * 16 + cl;

        const float4* q4 = (const float4*)(qe + (size_t)row * DIM + half * 64);
        const float4* d4 = (const float4*)(de + (size_t)col * DIM + half * 64);
        float acc = 0.f;
#pragma unroll
        for (int k = 0; k < 16; k++) {
            float4 a = q4[k], b = d4[k];
            acc = fmaf(a.x, b.x, acc);
            acc = fmaf(a.y, b.y, acc);
            acc = fmaf(a.z, b.z, acc);
            acc = fmaf(a.w, b.w, acc);
        }
        float s = acc + __shfl_xor_sync(0xffffffffu, acc, 16);   // combine dim halves

        unsigned c = (unsigned)col;
#pragma unroll
        for (int off = 1; off < 16; off <<= 1) {
            float    os = __shfl_xor_sync(0xffffffffu, s, off);
            unsigned oc = __shfl_xor_sync(0xffffffffu, c, off);
            if (os > s || (os == s && oc < c)) { s = os; c = oc; }
        }
        if (lane == 0) atomicMax(&g_key[row], pack_key(s, c));
    }
}

// =====================================================================
// Pass 4: gather weights, normalized weighted sum
// =====================================================================
__global__ void finalize_kernel(const int* __restrict__ qids, const int* __restrict__ dids,
                                const float* __restrict__ qwt, const float* __restrict__ dwt,
                                float* __restrict__ out) {
    __shared__ float sA[256], sB[256], sC[256];
    int tid = threadIdx.x;
    float a = 0.f, b = 0.f, c = 0.f;
    for (int q = tid; q < Q_N; q += 256) {
        unsigned long long k = g_key[q];
        unsigned u    = (unsigned)(k >> 32);
        unsigned bits = (u & 0x80000000u) ? (u & 0x7FFFFFFFu) : ~u;
        float    ms   = __uint_as_float(bits);
        unsigned col  = 0xFFFFFFFFu - (unsigned)(k & 0xFFFFFFFFu);
        float comb = qwt[qids[q]] * dwt[dids[col]];
        a += comb; b += comb * ms; c += ms;
    }
    sA[tid] = a; sB[tid] = b; sC[tid] = c;
    __syncthreads();
    for (int off = 128; off > 0; off >>= 1) {
        if (tid < off) { sA[tid] += sA[tid + off]; sB[tid] += sB[tid + off]; sC[tid] += sC[tid + off]; }
        __syncthreads();
    }
    if (tid == 0) out[0] = (sA[0] > 0.f) ? (sB[0] / sA[0]) : (sC[0] / (float)Q_N);
}

// =====================================================================
// launch
// =====================================================================
extern "C" void kernel_launch(void* const* d_in, const int* in_sizes, int n_in,
                              void* d_out, int out_size) {
    const float* qe  = (const float*)d_in[0];
    const float* de  = (const float*)d_in[1];
    const int*   qid = (const int*)d_in[2];
    const int*   did = (const int*)d_in[3];
    const float* qwt = (const float*)d_in[4];
    const float* dwt = (const float*)d_in[5];
    float* out = (float*)d_out;

    size_t smem = (size_t)(3 * TILE_E) * sizeof(__nv_bfloat16);   // 104,448 B -> 2 CTAs/SM
    cudaFuncSetAttribute(approx_kernel, cudaFuncAttributeMaxDynamicSharedMemorySize, (int)smem);

    convert_kernel<<<D_N * DIM / 8 / 256, 256>>>((const float4*)qe, (const float4*)de);
    approx_kernel<<<dim3(Q_N / TQ, NSLICE), 256, smem>>>();
    scan_kernel<<<Q_N, 256>>>();
    exact_kernel<<<256, 256>>>(qe, de);
    finalize_kernel<<<1, 256>>>(qid, did, qwt, dwt, out);
}